// round 17
// baseline (speedup 1.0000x reference)
#include <cuda_runtime.h>
#include <cuda_fp16.h>
#include <cstdint>

#define Bx 8
#define Nx 1024
#define Dx 768
#define Hx 12
#define DHx 64
#define BHx (Bx*Hx)
#define GK 768        // K dim of both dense GEMMs

static __constant__ float kSCALE = 0.03608439182435161f; // 768^-0.5

// ---------------- scratch (device globals, no allocation) ----------------
__device__ __align__(256) __half g_qh[BHx*Nx*DHx];                   // q*SCALE fp16
__device__ __align__(256) __half g_kh[BHx*Nx*DHx];                   // k fp16
__device__ __align__(256) __half g_vh[BHx*Nx*DHx];                   // v fp16

__device__ __align__(256) __half g_x[Bx*Nx*Dx];                      // x fp16
__device__ __align__(256) __half g_wqT[3*Dx*Dx];                     // W_qkv^T fp16 [2304,768]
__device__ __align__(256) __half g_wpT[Dx*Dx];                       // W_proj^T fp16
__device__ __align__(256) __half g_ao[Bx*Nx*Dx];                     // attention out fp16
__device__ __align__(256) __half g_dh[Nx*Nx];                        // dist fp16 [1024,1024]

// ====================== helpers ======================
__device__ __forceinline__ uint32_t smem_u32(const void* p) {
    uint32_t a;
    asm("{ .reg .u64 t; cvta.to.shared.u64 t, %1; cvt.u32.u64 %0, t; }" : "=r"(a) : "l"(p));
    return a;
}
__device__ __forceinline__ void cp16(uint32_t dst, const void* src) {
    asm volatile("cp.async.cg.shared.global [%0], [%1], 16;" :: "r"(dst), "l"(src));
}
__device__ __forceinline__ void ldsm_x4(uint32_t* r, uint32_t addr) {
    asm volatile("ldmatrix.sync.aligned.m8n8.x4.shared.b16 {%0,%1,%2,%3}, [%4];"
        : "=r"(r[0]), "=r"(r[1]), "=r"(r[2]), "=r"(r[3]) : "r"(addr));
}
__device__ __forceinline__ void ldsm_x4t(uint32_t* r, uint32_t addr) {
    asm volatile("ldmatrix.sync.aligned.m8n8.x4.trans.shared.b16 {%0,%1,%2,%3}, [%4];"
        : "=r"(r[0]), "=r"(r[1]), "=r"(r[2]), "=r"(r[3]) : "r"(addr));
}
__device__ __forceinline__ void mma16816(float* c, const uint32_t* a, const uint32_t* b) {
    asm volatile("mma.sync.aligned.m16n8k16.row.col.f32.f16.f16.f32 "
        "{%0,%1,%2,%3}, {%4,%5,%6,%7}, {%8,%9}, {%0,%1,%2,%3};"
        : "+f"(c[0]), "+f"(c[1]), "+f"(c[2]), "+f"(c[3])
        : "r"(a[0]), "r"(a[1]), "r"(a[2]), "r"(a[3]), "r"(b[0]), "r"(b[1]));
}
__device__ __forceinline__ uint32_t packh2(float f0, float f1) {
    union { __half h[2]; uint32_t u; } P;
    P.h[0] = __float2half_rn(f0);
    P.h[1] = __float2half_rn(f1);
    return P.u;
}
__device__ __forceinline__ uint32_t lds_b32(uint32_t addr) {
    uint32_t v;
    asm volatile("ld.shared.b32 %0, [%1];" : "=r"(v) : "r"(addr));
    return v;
}
__device__ __forceinline__ uint32_t ex2_h2(uint32_t e) {
    uint32_t r;
    asm volatile("ex2.approx.f16x2 %0, %1;" : "=r"(r) : "r"(e));
    return r;
}

// ====================== fused conversion kernel ======================
#define WQ_BLOCKS 1728
#define WP_BLOCKS 576
#define X_BLOCKS  6144
#define D_BLOCKS  1024
#define CONV_BLOCKS (WQ_BLOCKS + WP_BLOCKS + X_BLOCKS + D_BLOCKS)

__global__ void __launch_bounds__(256)
conv_all(const float* __restrict__ X, const float* __restrict__ D,
         const float* __restrict__ Wq, const float* __restrict__ Wp)
{
    __shared__ float t[32][33];
    const int blk = blockIdx.x;
    const int tid = threadIdx.x;

    if (blk < WQ_BLOCKS + WP_BLOCKS) {
        const float* W;
        __half* Th;
        int N, bx, by;
        if (blk < WQ_BLOCKS) {
            W = Wq; Th = g_wqT; N = 3 * Dx;
            bx = (blk % 72) * 32; by = (blk / 72) * 32;
        } else {
            int b2 = blk - WQ_BLOCKS;
            W = Wp; Th = g_wpT; N = Dx;
            bx = (b2 % 24) * 32; by = (b2 / 24) * 32;
        }
        const int txx = tid & 31, tyy = tid >> 5;
#pragma unroll
        for (int r = 0; r < 4; r++)
            t[tyy + 8 * r][txx] = W[(size_t)(by + tyy + 8 * r) * N + bx + txx];
        __syncthreads();
#pragma unroll
        for (int r = 0; r < 4; r++) {
            int nrow = bx + tyy + 8 * r;
            Th[(size_t)nrow * GK + by + txx] = __float2half_rn(t[txx][tyy + 8 * r]);
        }
    } else {
        int b2 = blk - (WQ_BLOCKS + WP_BLOCKS);
        const float* src;
        __half* dst;
        int i;
        if (b2 < X_BLOCKS) { src = X; dst = g_x;  i = b2 * 256 + tid; }
        else               { src = D; dst = g_dh; i = (b2 - X_BLOCKS) * 256 + tid; }
        float4 v = ((const float4*)src)[i];
        union { __half h[4]; uint2 u; } p;
        p.h[0] = __float2half_rn(v.x);
        p.h[1] = __float2half_rn(v.y);
        p.h[2] = __float2half_rn(v.z);
        p.h[3] = __float2half_rn(v.w);
        ((uint2*)dst)[i] = p.u;
    }
}

// ====================== fp16 HMMA GEMM0 (128x128, BK=64, 3-stage) ======================
#define BKc 64
#define ROWB 144                       // 128B data + 16B pad
#define STG_ARR (128 * ROWB)           // 18432
#define STAGE_BYTES (2 * STG_ARR)      // 36864 (A, B)
#define GEMM_SMEM (3 * STAGE_BYTES)    // 110592

__global__ void __launch_bounds__(256, 2)
mma_gemm0(const float* __restrict__ bias)
{
    extern __shared__ __align__(128) char dyn[];
    const uint32_t sbase = smem_u32(dyn);

    const int tid = threadIdx.x;
    const int lane = tid & 31, wid = tid >> 5;
    const int mb = blockIdx.y * 128;
    const int nb = blockIdx.x * 128;
    const int m0 = (wid & 3) * 32;
    const int n0 = (wid >> 2) * 64;

    auto load_chunk = [&](int c, int buf) {
        const uint32_t sb = sbase + buf * STAGE_BYTES;
#pragma unroll
        for (int i = 0; i < 8; i++) {
            int id  = tid + 256 * i;        // 0..2047
            int arr = id >> 10;
            int idx = id & 1023;
            int row = idx >> 3;
            int ch  = idx & 7;
            int grow = (arr ? nb : mb) + row;
            const __half* src = (arr ? g_wqT : g_x) + (size_t)grow * GK + c * BKc + ch * 8;
            cp16(sb + arr * STG_ARR + row * ROWB + ch * 16, src);
        }
        asm volatile("cp.async.commit_group;");
    };

    float acc[2][8][4];
#pragma unroll
    for (int mf = 0; mf < 2; mf++)
#pragma unroll
        for (int nf = 0; nf < 8; nf++)
#pragma unroll
            for (int r = 0; r < 4; r++) acc[mf][nf][r] = 0.f;

    const uint32_t fr_off = (lane & 15) * ROWB + (lane >> 4) * 16;
    const int NCH = GK / BKc;   // 12

    load_chunk(0, 0);
    load_chunk(1, 1);

    for (int c = 0; c < NCH; c++) {
        const int buf = c % 3;
        if (c + 2 < NCH) {
            asm volatile("cp.async.wait_group 1;");
        } else {
            asm volatile("cp.async.wait_group 0;");
        }
        __syncthreads();
        if (c + 2 < NCH) load_chunk(c + 2, (c + 2) % 3);

        const uint32_t sb = sbase + buf * STAGE_BYTES;
        const uint32_t aH = sb, bH = sb + STG_ARR;

#pragma unroll
        for (int ks = 0; ks < 4; ks++) {
            uint32_t ah[2][4];
#pragma unroll
            for (int mf = 0; mf < 2; mf++) {
                uint32_t ra = (uint32_t)(m0 + mf * 16) * ROWB + fr_off + ks * 32;
                ldsm_x4(ah[mf], aH + ra);
            }
#pragma unroll
            for (int p = 0; p < 4; p++) {
                uint32_t rb = (uint32_t)(n0 + p * 16) * ROWB + fr_off + ks * 32;
                uint32_t t[4];
                ldsm_x4(t, bH + rb);
                uint32_t bh0[2] = { t[0], t[2] }, bh1[2] = { t[1], t[3] };
#pragma unroll
                for (int mf = 0; mf < 2; mf++) {
                    mma16816(acc[mf][p*2  ], ah[mf], bh0);
                    mma16816(acc[mf][p*2+1], ah[mf], bh1);
                }
            }
        }
        __syncthreads();
    }

    // ---------------- epilogue: scatter q/k/v ----------------
    const int s   = nb / Dx;
    const int nbr = nb - s * Dx;
#pragma unroll
    for (int mf = 0; mf < 2; mf++)
#pragma unroll
        for (int nf = 0; nf < 8; nf++) {
            const int ncol = n0 + nf * 8 + (lane & 3) * 2;
            const int gn   = nb + ncol;
            const float b0 = bias[gn], b1 = bias[gn + 1];
            const int rowa = mb + m0 + mf * 16 + (lane >> 2);
#pragma unroll
            for (int half = 0; half < 2; half++) {
                const int m = rowa + half * 8;
                float v0 = acc[mf][nf][half * 2 + 0] + b0;
                float v1 = acc[mf][nf][half * 2 + 1] + b1;
                const int bi = m >> 10, n = m & 1023;
                const int rc = nbr + ncol;
                const int hh = rc >> 6, d = rc & 63;
                size_t idx = (((size_t)(bi * Hx + hh)) * Nx + n) * DHx + d;
                if (s == 0) {
                    *(uint32_t*)&g_qh[idx] = packh2(v0 * kSCALE, v1 * kSCALE);
                } else if (s == 1) {
                    *(uint32_t*)&g_kh[idx] = packh2(v0, v1);
                } else {
                    *(uint32_t*)&g_vh[idx] = packh2(v0, v1);
                }
            }
        }
}

// ====================== fp16 HMMA proj GEMM (64x256 tile, 2-stage) ======================
// Doubles per-CTA MMA work vs 64x128 at the same sync count; inner loop has
// GEMM0's proven 1:2.67 ldsm:MMA shape (warp tile 32x64).
#define PA_ARR (64 * ROWB)             // 9216
#define PB_ARR (256 * ROWB)            // 36864
#define PSTAGE (PA_ARR + PB_ARR)       // 46080
#define PROJ_SMEM (2 * PSTAGE)         // 92160

__global__ void __launch_bounds__(256, 2)
mma_proj(const float* __restrict__ bias, float* __restrict__ Cout)
{
    extern __shared__ __align__(128) char dyn[];
    const uint32_t sbase = smem_u32(dyn);

    const int tid = threadIdx.x;
    const int lane = tid & 31, wid = tid >> 5;
    const int mb = blockIdx.y * 64;
    const int nb = blockIdx.x * 256;
    const int m0 = (wid & 1) * 32;     // 2 warps along M
    const int n0 = (wid >> 1) * 64;    // 4 warps along N (64 cols each)

    auto load_chunk = [&](int c, int buf) {
        const uint32_t sb = sbase + buf * PSTAGE;
#pragma unroll
        for (int i = 0; i < 10; i++) {
            int id = tid + 256 * i;         // 0..2559
            if (id < 512) {                 // A: 64 rows
                int row = id >> 3, ch = id & 7;
                cp16(sb + row * ROWB + ch * 16,
                     g_ao + (size_t)(mb + row) * GK + c * BKc + ch * 8);
            } else {                        // B: 256 rows
                int idx = id - 512;
                int row = idx >> 3, ch = idx & 7;
                cp16(sb + PA_ARR + row * ROWB + ch * 16,
                     g_wpT + (size_t)(nb + row) * GK + c * BKc + ch * 8);
            }
        }
        asm volatile("cp.async.commit_group;");
    };

    float acc[2][8][4];
#pragma unroll
    for (int mf = 0; mf < 2; mf++)
#pragma unroll
        for (int nf = 0; nf < 8; nf++)
#pragma unroll
            for (int r = 0; r < 4; r++) acc[mf][nf][r] = 0.f;

    const uint32_t fr_off = (lane & 15) * ROWB + (lane >> 4) * 16;
    const int NCH = GK / BKc;   // 12

    load_chunk(0, 0);

    for (int c = 0; c < NCH; c++) {
        const int buf = c & 1;
        if (c + 1 < NCH) {
            load_chunk(c + 1, buf ^ 1);
            asm volatile("cp.async.wait_group 1;");
        } else {
            asm volatile("cp.async.wait_group 0;");
        }
        __syncthreads();

        const uint32_t sb = sbase + buf * PSTAGE;
        const uint32_t aH = sb, bH = sb + PA_ARR;

#pragma unroll
        for (int ks = 0; ks < 4; ks++) {
            uint32_t ah[2][4];
#pragma unroll
            for (int mf = 0; mf < 2; mf++) {
                uint32_t ra = (uint32_t)(m0 + mf * 16) * ROWB + fr_off + ks * 32;
                ldsm_x4(ah[mf], aH + ra);
            }
#pragma unroll
            for (int p = 0; p < 4; p++) {
                uint32_t rb = (uint32_t)(n0 + p * 16) * ROWB + fr_off + ks * 32;
                uint32_t t[4];
                ldsm_x4(t, bH + rb);
                uint32_t bh0[2] = { t[0], t[2] }, bh1[2] = { t[1], t[3] };
#pragma unroll
                for (int mf = 0; mf < 2; mf++) {
                    mma16816(acc[mf][p*2  ], ah[mf], bh0);
                    mma16816(acc[mf][p*2+1], ah[mf], bh1);
                }
            }
        }
        __syncthreads();
    }

    // ---------------- epilogue ----------------
#pragma unroll
    for (int mf = 0; mf < 2; mf++)
#pragma unroll
        for (int nf = 0; nf < 8; nf++) {
            const int ncol = n0 + nf * 8 + (lane & 3) * 2;
            const int gn   = nb + ncol;
            const float b0 = bias[gn], b1 = bias[gn + 1];
            const int rowa = mb + m0 + mf * 16 + (lane >> 2);
#pragma unroll
            for (int half = 0; half < 2; half++) {
                const int m = rowa + half * 8;
                float v0 = acc[mf][nf][half * 2 + 0] + b0;
                float v1 = acc[mf][nf][half * 2 + 1] + b1;
                *(float2*)&Cout[(size_t)m * Dx + gn] = make_float2(v0, v1);
            }
        }
}

// =====================================================================
// HMMA flash attention; softmax via ex2.approx.f16x2. Bounded-score
// form. dist staged via cp.async fp16 in the 3-stage ring; Q in regs.
// Stage layout: [Kh 64x144 | Vh 64x144 | Dh 128x144].
// =====================================================================
#define QSTR 144
#define KARR (64 * QSTR)               // 9216
#define DARR (128 * QSTR)              // 18432
#define ASTAGE (2 * KARR + DARR)       // 36864
#define ATTN_SMEM (3 * ASTAGE)         // 110592

__global__ void __launch_bounds__(256, 2)
attn_mma(const float* __restrict__ gamma)
{
    extern __shared__ __align__(128) char smn[];
    const uint32_t sb = smem_u32(smn);
    const uint32_t sQ = sb + 2 * ASTAGE;   // Q parks in stage-2 KV region

    const int qt = blockIdx.x, h = blockIdx.y, b = blockIdx.z;
    const int bh = b * Hx + h;
    const int q0 = qt * 128;
    const int tid = threadIdx.x, lane = tid & 31, wid = tid >> 5;

    const float LOG2E = 1.4426950408889634f;
    const float g  = gamma[b];
    const float gl = g * LOG2E;
    const float off = -2.0f * LOG2E;

    const __half* qh = g_qh + (size_t)bh * Nx * DHx;
    const __half* kvsrc[2] = {
        g_kh + (size_t)bh * Nx * DHx, g_vh + (size_t)bh * Nx * DHx };

    // Q tile load (once): 128 rows x 8 chunks of 16B
#pragma unroll
    for (int i = 0; i < 4; i++) {
        int id = tid + 256 * i;        // 0..1023
        int row = id >> 3, ch = id & 7;
        cp16(sQ + row * QSTR + ch * 16, qh + (size_t)(q0 + row) * DHx + ch * 8);
    }
    asm volatile("cp.async.commit_group;");

    auto load_kv = [&](int kt, int buf) {
        const uint32_t kb = sb + buf * ASTAGE;
        const int k0 = kt * 64;
#pragma unroll
        for (int i = 0; i < 4; i++) {   // K,V
            int id = tid + 256 * i;
            int arr = id >> 9;
            int idx = id & 511;
            int row = idx >> 3, ch = idx & 7;
            cp16(kb + arr * KARR + row * QSTR + ch * 16,
                 kvsrc[arr] + (size_t)(k0 + row) * DHx + ch * 8);
        }
#pragma unroll
        for (int i = 0; i < 4; i++) {   // dist fp16 tile 128x64
            int id = tid + 256 * i;
            int row = id >> 3, ch = id & 7;
            cp16(kb + 2 * KARR + row * QSTR + ch * 16,
                 g_dh + (size_t)(q0 + row) * Nx + k0 + ch * 8);
        }
        asm volatile("cp.async.commit_group;");
    };
    load_kv(0, 0);
    load_kv(1, 1);

    const uint32_t fr_off = (lane & 15) * QSTR + (lane >> 4) * 16;

    // wait for Q group only, hoist Q frags
    asm volatile("cp.async.wait_group 2;");
    __syncthreads();
    uint32_t qf[4][4];
#pragma unroll
    for (int ks = 0; ks < 4; ks++) {
        uint32_t ra = (uint32_t)(wid * 16) * QSTR + fr_off + ks * 32;
        ldsm_x4(qf[ks], sQ + ra);
    }

    float accO[8][4];
#pragma unroll
    for (int nf = 0; nf < 8; nf++)
#pragma unroll
        for (int r = 0; r < 4; r++) accO[nf][r] = 0.f;
    float lrow0 = 0.f, lrow1 = 0.f;

    const uint32_t dlocal = (uint32_t)(wid * 16 + (lane >> 2)) * QSTR
                          + (lane & 3) * 4;

    for (int kt = 0; kt < 16; kt++) {
        const int buf = kt % 3;
        if (kt + 2 < 16) {
            asm volatile("cp.async.wait_group 1;");
        } else {
            asm volatile("cp.async.wait_group 0;");
        }
        __syncthreads();
        if (kt + 2 < 16) load_kv(kt + 2, (kt + 2) % 3);

        const uint32_t kb = sb + buf * ASTAGE;

        // ---- S = Q K^T ----
        float accS[8][4];
#pragma unroll
        for (int nf = 0; nf < 8; nf++)
#pragma unroll
            for (int r = 0; r < 4; r++) accS[nf][r] = 0.f;

#pragma unroll
        for (int ks = 0; ks < 4; ks++) {
#pragma unroll
            for (int p = 0; p < 4; p++) {
                uint32_t rb = (uint32_t)(p * 16) * QSTR + fr_off + ks * 32;
                uint32_t t[4];
                ldsm_x4(t, kb + rb);                 // Kh
                uint32_t bh0[2] = { t[0], t[2] }, bh1[2] = { t[1], t[3] };
                mma16816(accS[p*2  ], qf[ks], bh0);
                mma16816(accS[p*2+1], qf[ks], bh1);
            }
        }

        // ---- bias + ex2.f16x2 softmax numerator (P in packed fp16) ----
        const uint32_t dbs = kb + 2 * KARR + dlocal;
        uint32_t pw0[8], pw1[8];
#pragma unroll
        for (int nf = 0; nf < 8; nf++) {
            union { uint32_t u; __half2 h; } w0, w1;
            w0.u = lds_b32(dbs + nf * 16);
            w1.u = lds_b32(dbs + 8 * QSTR + nf * 16);
            float2 d0 = __half22float2(w0.h);
            float2 d1 = __half22float2(w1.h);
            float e00 = fmaf(accS[nf][0], LOG2E, fmaf(d0.x, -gl, off));
            float e01 = fmaf(accS[nf][1], LOG2E, fmaf(d0.y, -gl, off));
            float e10 = fmaf(accS[nf][2], LOG2E, fmaf(d1.x, -gl, off));
            float e11 = fmaf(accS[nf][3], LOG2E, fmaf(d1.y, -gl, off));
            pw0[nf] = ex2_h2(packh2(e00, e01));
            pw1[nf] = ex2_h2(packh2(e10, e11));
            float2 f0 = __half22float2(*(__half2*)&pw0[nf]);
            float2 f1 = __half22float2(*(__half2*)&pw1[nf]);
            lrow0 += f0.x + f0.y;
            lrow1 += f1.x + f1.y;
        }

        // ---- O += P V ----
#pragma unroll
        for (int kg = 0; kg < 4; kg++) {
            uint32_t pah[4] = { pw0[2*kg], pw1[2*kg], pw0[2*kg+1], pw1[2*kg+1] };
#pragma unroll
            for (int nfp = 0; nfp < 4; nfp++) {
                uint32_t addr = (uint32_t)(kg * 16 + (lane & 15)) * QSTR
                              + nfp * 32 + (lane >> 4) * 16;
                uint32_t t[4];
                ldsm_x4t(t, kb + KARR + addr);        // Vh
                uint32_t bh0[2] = { t[0], t[1] }, bh1[2] = { t[2], t[3] };
                mma16816(accO[2*nfp  ], pah, bh0);
                mma16816(accO[2*nfp+1], pah, bh1);
            }
        }
    }

    // ---- final row-sum reduction + normalize + fp16 store ----
    lrow0 += __shfl_xor_sync(0xffffffffu, lrow0, 1);
    lrow0 += __shfl_xor_sync(0xffffffffu, lrow0, 2);
    lrow1 += __shfl_xor_sync(0xffffffffu, lrow1, 1);
    lrow1 += __shfl_xor_sync(0xffffffffu, lrow1, 2);
    const float inv0 = 1.f / lrow0, inv1 = 1.f / lrow1;
    const int mg = q0 + wid * 16 + (lane >> 2);
#pragma unroll
    for (int nf = 0; nf < 8; nf++) {
        const int d = nf * 8 + 2 * (lane & 3);
        size_t base0 = ((size_t)b * Nx + mg) * Dx + h * 64 + d;
        size_t base1 = base0 + (size_t)8 * Dx;
        *(uint32_t*)&g_ao[base0] = packh2(accO[nf][0] * inv0, accO[nf][1] * inv0);
        *(uint32_t*)&g_ao[base1] = packh2(accO[nf][2] * inv1, accO[nf][3] * inv1);
    }
}

// =====================================================================
extern "C" void kernel_launch(void* const* d_in, const int* in_sizes, int n_in,
                              void* d_out, int out_size)
{
    const float* x      = (const float*)d_in[0];
    const float* gamma  = (const float*)d_in[1];
    const float* dist   = (const float*)d_in[2];
    const float* W_qkv  = (const float*)d_in[3];
    const float* b_qkv  = (const float*)d_in[4];
    const float* W_proj = (const float*)d_in[5];
    const float* b_proj = (const float*)d_in[6];
    float* out = (float*)d_out;

    cudaFuncSetAttribute(attn_mma,
                         cudaFuncAttributeMaxDynamicSharedMemorySize, ATTN_SMEM);
    cudaFuncSetAttribute(mma_gemm0,
                         cudaFuncAttributeMaxDynamicSharedMemorySize, GEMM_SMEM);
    cudaFuncSetAttribute(mma_proj,
                         cudaFuncAttributeMaxDynamicSharedMemorySize, PROJ_SMEM);

    // 0) all precision conversions in one launch
    conv_all<<<CONV_BLOCKS, 256>>>(x, dist, W_qkv, W_proj);

    // 1) QKV projection -> fp16 q(*SCALE) / k / v in [B,H,N,DH]
    mma_gemm0<<<dim3(3 * Dx / 128, Bx * Nx / 128), 256, GEMM_SMEM>>>(b_qkv);

    // 2) HMMA flash attention -> g_ao (fp16)
    attn_mma<<<dim3(Nx / 128, Hx, Bx), 256, ATTN_SMEM>>>(gamma);

    // 3) output projection (64x256 tiles, 2-stage, 2 CTAs/SM)
    mma_proj<<<dim3(Dx / 256, Bx * Nx / 64), 256, PROJ_SMEM>>>(b_proj, out);
}